// round 6
// baseline (speedup 1.0000x reference)
#include <cuda_runtime.h>
#include <cstdint>

#define N_NODES 100000
#define N_EDGES 1600000
#define F_IN    128
#define HDIM    64
#define TILE_N  32
#define NTH     256
#define NUM_TILES (N_NODES / TILE_N)   // 3125, exact

// ---------------- device scratch (static: no allocation allowed) ----------------
__device__ float g_Kf[N_NODES * HDIM];   // key per node
__device__ float g_Qf[N_NODES * HDIM];   // query per node
__device__ float g_Vf[N_NODES * HDIM];   // value per node
__device__ float g_Sk[N_NODES * HDIM];   // skip term: h@Ws^T + b_gate
__device__ int   g_counts[N_NODES];
__device__ int   g_rowstart[N_NODES + 1];
__device__ int   g_cursor[N_NODES];
__device__ int   g_sorted_src[N_EDGES];
__device__ int   g_is64;                 // edge_index dtype flag

// ---------------- edge dtype probe ----------------
// int64 indices in [0,1e5) have zero high words; int32 data read as u64 pairs
// has a random index in the high word (zero w.p. 1e-5). 512 zeros => int64.
__global__ void detect_dtype_kernel(const void* __restrict__ ei)
{
    if (threadIdx.x == 0 && blockIdx.x == 0) {
        const unsigned long long* p = (const unsigned long long*)ei;
        int is64 = 1;
        for (int i = 0; i < 512; i++) {
            if ((p[i] >> 32) != 0ull) { is64 = 0; break; }
        }
        g_is64 = is64;
    }
}

__device__ __forceinline__ int edge_at(const void* __restrict__ ei, int pos, int is64)
{
    if (is64) return (int)((const long long*)ei)[pos];
    return ((const int*)ei)[pos];
}

// ---------------- fused node kernel: MLP + k/q/v + skip ----------------
// Static shared only (<48KB): one weight buffer reused across all 6 GEMMs.
struct SmemT {
    __align__(16) float Wbuf[64 * 68];      // k-major weight chunk
    __align__(16) float Xbuf[TILE_N * 132]; // layer-1 input (reused as H2)
    __align__(16) float H1buf[TILE_N * 68];
    float biasS[6 * 64];
};

__device__ __forceinline__ void stage_w(float* __restrict__ Wbuf,
                                        const float* __restrict__ W,
                                        int ldw, int kofs)
{
    #pragma unroll
    for (int idx = threadIdx.x; idx < 64 * 64; idx += NTH) {
        int f = idx >> 6, k = idx & 63;
        Wbuf[k * 68 + f] = W[f * ldw + kofs + k];
    }
}

__device__ __forceinline__ void gemm_accum(const float* __restrict__ In, int ldin, int kbase,
                                           const float* __restrict__ Wbuf,
                                           float acc[2][4], int tf, int tn)
{
    const float* in0 = In + (tn * 2 + 0) * ldin + kbase;
    const float* in1 = In + (tn * 2 + 1) * ldin + kbase;
    #pragma unroll 8
    for (int k = 0; k < 64; k++) {
        float4 w = *(const float4*)&Wbuf[k * 68 + tf * 4];
        float x0 = in0[k], x1 = in1[k];
        acc[0][0] += x0 * w.x; acc[0][1] += x0 * w.y; acc[0][2] += x0 * w.z; acc[0][3] += x0 * w.w;
        acc[1][0] += x1 * w.x; acc[1][1] += x1 * w.y; acc[1][2] += x1 * w.z; acc[1][3] += x1 * w.w;
    }
}

__device__ __forceinline__ void init_acc(const float* __restrict__ biasS, int boff,
                                         float acc[2][4], int tf)
{
    #pragma unroll
    for (int fi = 0; fi < 4; fi++) {
        float b = biasS[boff + tf * 4 + fi];
        acc[0][fi] = b; acc[1][fi] = b;
    }
}

__device__ __forceinline__ void store_head(float* __restrict__ out, int nb,
                                           int tf, int tn, float acc[2][4])
{
    #pragma unroll
    for (int ni = 0; ni < 2; ni++) {
        int node = nb + tn * 2 + ni;
        float4 v = make_float4(acc[ni][0], acc[ni][1], acc[ni][2], acc[ni][3]);
        *(float4*)&out[node * HDIM + tf * 4] = v;
    }
}

__global__ void __launch_bounds__(NTH)
node_kernel(const float* __restrict__ x,
            const float* __restrict__ W1, const float* __restrict__ b1,
            const float* __restrict__ W2, const float* __restrict__ b2,
            const float* __restrict__ Wk, const float* __restrict__ bk,
            const float* __restrict__ Wq, const float* __restrict__ bq,
            const float* __restrict__ Wv, const float* __restrict__ bv,
            const float* __restrict__ Ws, const float* __restrict__ bgate)
{
    __shared__ SmemT sm;
    const int tid = threadIdx.x;
    const int nb  = blockIdx.x * TILE_N;
    const int tf  = tid & 15;
    const int tn  = tid >> 4;

    for (int idx = tid; idx < TILE_N * F_IN; idx += NTH) {
        int n = idx >> 7, k = idx & 127;
        sm.Xbuf[n * 132 + k] = x[(nb + n) * F_IN + k];
    }
    if (tid < HDIM) {
        sm.biasS[tid]       = b1[tid];
        sm.biasS[64 + tid]  = b2[tid];
        sm.biasS[128 + tid] = bk[tid];
        sm.biasS[192 + tid] = bq[tid];
        sm.biasS[256 + tid] = bv[tid];
        sm.biasS[320 + tid] = bgate[tid];
    }
    stage_w(sm.Wbuf, W1, F_IN, 0);
    __syncthreads();

    float acc[2][4];

    // layer 1: relu(x @ W1^T + b1), K=128 in two chunks
    init_acc(sm.biasS, 0, acc, tf);
    gemm_accum(sm.Xbuf, 132, 0, sm.Wbuf, acc, tf, tn);
    __syncthreads();
    stage_w(sm.Wbuf, W1, F_IN, 64);
    __syncthreads();
    gemm_accum(sm.Xbuf, 132, 64, sm.Wbuf, acc, tf, tn);
    #pragma unroll
    for (int ni = 0; ni < 2; ni++) {
        float4 v = make_float4(fmaxf(acc[ni][0], 0.f), fmaxf(acc[ni][1], 0.f),
                               fmaxf(acc[ni][2], 0.f), fmaxf(acc[ni][3], 0.f));
        *(float4*)&sm.H1buf[(tn * 2 + ni) * 68 + tf * 4] = v;
    }
    __syncthreads();

    // layer 2: h = h1 @ W2^T + b2 -> stored into Xbuf region (X is dead)
    stage_w(sm.Wbuf, W2, HDIM, 0);
    __syncthreads();
    init_acc(sm.biasS, 64, acc, tf);
    gemm_accum(sm.H1buf, 68, 0, sm.Wbuf, acc, tf, tn);
    float* H2 = sm.Xbuf;
    #pragma unroll
    for (int ni = 0; ni < 2; ni++) {
        float4 v = make_float4(acc[ni][0], acc[ni][1], acc[ni][2], acc[ni][3]);
        *(float4*)&H2[(tn * 2 + ni) * 68 + tf * 4] = v;
    }
    __syncthreads();

    // heads: k, q, v, skip
    const float* Wh[4]   = { Wk, Wq, Wv, Ws };
    const int    boff[4] = { 128, 192, 256, 320 };
    float* outp[4]       = { g_Kf, g_Qf, g_Vf, g_Sk };
    #pragma unroll 1
    for (int h = 0; h < 4; h++) {
        stage_w(sm.Wbuf, Wh[h], HDIM, 0);
        __syncthreads();
        init_acc(sm.biasS, boff[h], acc, tf);
        gemm_accum(H2, 68, 0, sm.Wbuf, acc, tf, tn);
        store_head(outp[h], nb, tf, tn, acc);
        __syncthreads();
    }
}

// ---------------- CSR build ----------------
__global__ void zero_counts_kernel()
{
    int i = blockIdx.x * blockDim.x + threadIdx.x;
    if (i < N_NODES) g_counts[i] = 0;
}

__global__ void hist_kernel(const void* __restrict__ ei)
{
    int e = blockIdx.x * blockDim.x + threadIdx.x;
    if (e < N_EDGES) {
        int is64 = g_is64;
        int d = edge_at(ei, N_EDGES + e, is64);
        if ((unsigned)d < (unsigned)N_NODES)
            atomicAdd(&g_counts[d], 1);
    }
}

__global__ void scan_kernel()
{
    __shared__ int wsums[32];
    __shared__ int carry_s;
    const int tid  = threadIdx.x;
    const int lane = tid & 31;
    const int wid  = tid >> 5;
    if (tid == 0) carry_s = 0;
    __syncthreads();

    for (int base = 0; base < N_NODES; base += 1024) {
        int v = (base + tid < N_NODES) ? g_counts[base + tid] : 0;
        int s = v;
        #pragma unroll
        for (int o = 1; o < 32; o <<= 1) {
            int t = __shfl_up_sync(0xffffffffu, s, o);
            if (lane >= o) s += t;
        }
        if (lane == 31) wsums[wid] = s;
        __syncthreads();
        if (wid == 0) {
            int ws = wsums[lane];
            #pragma unroll
            for (int o = 1; o < 32; o <<= 1) {
                int t = __shfl_up_sync(0xffffffffu, ws, o);
                if (lane >= o) ws += t;
            }
            wsums[lane] = ws;
        }
        __syncthreads();
        int offset = (wid > 0) ? wsums[wid - 1] : 0;
        int incl = s + offset;
        int excl = incl - v + carry_s;
        if (base + tid < N_NODES) {
            g_rowstart[base + tid] = excl;
            g_cursor[base + tid]   = excl;
        }
        __syncthreads();
        if (tid == 1023) carry_s += incl;
        __syncthreads();
    }
    if (tid == 0) g_rowstart[N_NODES] = carry_s;
}

__global__ void scatter_kernel(const void* __restrict__ ei)
{
    int e = blockIdx.x * blockDim.x + threadIdx.x;
    if (e < N_EDGES) {
        int is64 = g_is64;
        int s = edge_at(ei, e, is64);
        int d = edge_at(ei, N_EDGES + e, is64);
        if ((unsigned)d < (unsigned)N_NODES && (unsigned)s < (unsigned)N_NODES) {
            int pos = atomicAdd(&g_cursor[d], 1);
            if ((unsigned)pos < (unsigned)N_EDGES)
                g_sorted_src[pos] = s;
        }
    }
}

// ---------------- aggregate + fused scorer: one warp per destination node ----------------
__global__ void aggregate_kernel(const float* __restrict__ Wsc,
                                 const float* __restrict__ bsc,
                                 float* __restrict__ score)
{
    int warp = (blockIdx.x * blockDim.x + threadIdx.x) >> 5;
    int lane = threadIdx.x & 31;
    if (warp >= N_NODES) return;
    const int i = warp;

    float2 kv = *(const float2*)&g_Kf[i * HDIM + lane * 2];
    float ax = 0.f, ay = 0.f;

    int start = g_rowstart[i];
    int end   = g_rowstart[i + 1];
    for (int b = start; b < end; b += 32) {
        int m = end - b; if (m > 32) m = 32;
        int j = 0;
        if (lane < m) j = g_sorted_src[b + lane];
        for (int t = 0; t < m; t++) {
            int jj = __shfl_sync(0xffffffffu, j, t);
            float2 qv = *(const float2*)&g_Qf[jj * HDIM + lane * 2];
            float2 vv = *(const float2*)&g_Vf[jj * HDIM + lane * 2];
            float gx = kv.x + qv.x;
            float gy = kv.y + qv.y;
            float sx = __fdividef(1.0f, 1.0f + __expf(-gx));
            float sy = __fdividef(1.0f, 1.0f + __expf(-gy));
            ax += sx * vv.x;
            ay += sy * vv.y;
        }
    }

    float2 sk = *(const float2*)&g_Sk[i * HDIM + lane * 2];
    ax += sk.x; ay += sk.y;

    float2 w = *(const float2*)&Wsc[lane * 2];
    float p = ax * w.x + ay * w.y;
    #pragma unroll
    for (int o = 16; o > 0; o >>= 1) p += __shfl_down_sync(0xffffffffu, p, o);
    if (lane == 0) score[i] = p + bsc[0];
}

// ---------------- launch (kernel launches ONLY) ----------------
extern "C" void kernel_launch(void* const* d_in, const int* in_sizes, int n_in,
                              void* d_out, int out_size)
{
    const float* x     = (const float*)d_in[0];
    const void*  ei    = d_in[1];
    const float* W1    = (const float*)d_in[2];
    const float* b1    = (const float*)d_in[3];
    const float* W2    = (const float*)d_in[4];
    const float* b2    = (const float*)d_in[5];
    const float* Wk    = (const float*)d_in[6];
    const float* bk    = (const float*)d_in[7];
    const float* Wq    = (const float*)d_in[8];
    const float* bq    = (const float*)d_in[9];
    const float* Wv    = (const float*)d_in[10];
    const float* bv    = (const float*)d_in[11];
    const float* Ws    = (const float*)d_in[12];
    const float* bgate = (const float*)d_in[13];
    const float* Wsc   = (const float*)d_in[14];
    const float* bsc   = (const float*)d_in[15];
    float* score = (float*)d_out;

    detect_dtype_kernel<<<1, 32>>>(ei);

    node_kernel<<<NUM_TILES, NTH>>>(x, W1, b1, W2, b2, Wk, bk,
                                    Wq, bq, Wv, bv, Ws, bgate);

    zero_counts_kernel<<<(N_NODES + 255) / 256, 256>>>();
    hist_kernel<<<(N_EDGES + 255) / 256, 256>>>(ei);
    scan_kernel<<<1, 1024>>>();
    scatter_kernel<<<(N_EDGES + 255) / 256, 256>>>(ei);

    int agg_blocks = (N_NODES * 32 + 255) / 256;
    aggregate_kernel<<<agg_blocks, 256>>>(Wsc, bsc, score);
}

// round 7
// speedup vs baseline: 1.1944x; 1.1944x over previous
#include <cuda_runtime.h>
#include <cstdint>

#define N_NODES 100000
#define N_EDGES 1600000
#define F_IN    128
#define HDIM    64
#define TILE_N  32
#define NTH     256
#define NUM_TILES (N_NODES / TILE_N)   // 3125, exact
#define SCAN_BLK 1024
#define NBLK ((N_NODES + SCAN_BLK - 1) / SCAN_BLK)   // 98

// ---------------- device scratch (static: no allocation allowed) ----------------
__device__ float g_Kf[N_NODES * HDIM];
__device__ float g_Qf[N_NODES * HDIM];
__device__ float g_Vf[N_NODES * HDIM];
__device__ float g_Sk[N_NODES * HDIM];
__device__ int   g_counts[N_NODES];
__device__ int   g_rowstart[N_NODES + 1];
__device__ int   g_cursor[N_NODES];
__device__ int   g_sorted_src[N_EDGES];
__device__ int   g_blocksums[128];
__device__ int   g_blockoffs[128];
__device__ int   g_is64;

// ---------------- f32x2 packed helpers ----------------
__device__ __forceinline__ unsigned long long pack2(float v) {
    unsigned long long r; unsigned u = __float_as_uint(v);
    asm("mov.b64 %0, {%1, %1};" : "=l"(r) : "r"(u));
    return r;
}
__device__ __forceinline__ unsigned long long pk2(float lo, float hi) {
    unsigned long long r;
    asm("mov.b64 %0, {%1, %2};" : "=l"(r) : "r"(__float_as_uint(lo)), "r"(__float_as_uint(hi)));
    return r;
}
__device__ __forceinline__ float2 unpk(unsigned long long v) {
    unsigned lo, hi;
    asm("mov.b64 {%0, %1}, %2;" : "=r"(lo), "=r"(hi) : "l"(v));
    return make_float2(__uint_as_float(lo), __uint_as_float(hi));
}
__device__ __forceinline__ void ffma2(unsigned long long& acc,
                                      unsigned long long a, unsigned long long b) {
    asm("fma.rn.f32x2 %0, %1, %2, %0;" : "+l"(acc) : "l"(a), "l"(b));
}

// ---------------- edge dtype probe ----------------
__global__ void detect_dtype_kernel(const void* __restrict__ ei)
{
    if (threadIdx.x == 0 && blockIdx.x == 0) {
        const unsigned long long* p = (const unsigned long long*)ei;
        int is64 = 1;
        for (int i = 0; i < 512; i++) {
            if ((p[i] >> 32) != 0ull) { is64 = 0; break; }
        }
        g_is64 = is64;
    }
}

__device__ __forceinline__ int edge_at(const void* __restrict__ ei, int pos, int is64)
{
    if (is64) return (int)((const long long*)ei)[pos];
    return ((const int*)ei)[pos];
}

// ---------------- fused node kernel ----------------
struct SmemT {
    __align__(16) float Wbuf[64 * 68];
    __align__(16) float Xbuf[TILE_N * 132];
    __align__(16) float H1buf[TILE_N * 68];
    float biasS[6 * 64];
};

__device__ __forceinline__ void stage_w(float* __restrict__ Wbuf,
                                        const float* __restrict__ W,
                                        int ldw, int kofs)
{
    #pragma unroll
    for (int idx = threadIdx.x; idx < 64 * 64; idx += NTH) {
        int f = idx >> 6, k = idx & 63;
        Wbuf[k * 68 + f] = W[f * ldw + kofs + k];
    }
}

// acc[node 0..1][pair 0..1], each pair = 2 packed fp32 features
__device__ __forceinline__ void gemm_accum2(const float* __restrict__ In, int ldin, int kbase,
                                            const float* __restrict__ Wbuf,
                                            unsigned long long acc[2][2], int tf, int tn)
{
    const float* in0 = In + (tn * 2 + 0) * ldin + kbase;
    const float* in1 = In + (tn * 2 + 1) * ldin + kbase;
    #pragma unroll 8
    for (int k = 0; k < 64; k++) {
        const ulonglong2 w = *(const ulonglong2*)&Wbuf[k * 68 + tf * 4];
        unsigned long long x0 = pack2(in0[k]);
        unsigned long long x1 = pack2(in1[k]);
        ffma2(acc[0][0], x0, w.x); ffma2(acc[0][1], x0, w.y);
        ffma2(acc[1][0], x1, w.x); ffma2(acc[1][1], x1, w.y);
    }
}

__device__ __forceinline__ void init_acc2(const float* __restrict__ biasS, int boff,
                                          unsigned long long acc[2][2], int tf)
{
    unsigned long long p0 = pk2(biasS[boff + tf * 4 + 0], biasS[boff + tf * 4 + 1]);
    unsigned long long p1 = pk2(biasS[boff + tf * 4 + 2], biasS[boff + tf * 4 + 3]);
    acc[0][0] = p0; acc[0][1] = p1;
    acc[1][0] = p0; acc[1][1] = p1;
}

__device__ __forceinline__ void store_head2(float* __restrict__ out, int nb,
                                            int tf, int tn, unsigned long long acc[2][2])
{
    #pragma unroll
    for (int ni = 0; ni < 2; ni++) {
        int node = nb + tn * 2 + ni;
        float2 a = unpk(acc[ni][0]);
        float2 b = unpk(acc[ni][1]);
        *(float4*)&out[node * HDIM + tf * 4] = make_float4(a.x, a.y, b.x, b.y);
    }
}

__global__ void __launch_bounds__(NTH)
node_kernel(const float* __restrict__ x,
            const float* __restrict__ W1, const float* __restrict__ b1,
            const float* __restrict__ W2, const float* __restrict__ b2,
            const float* __restrict__ Wk, const float* __restrict__ bk,
            const float* __restrict__ Wq, const float* __restrict__ bq,
            const float* __restrict__ Wv, const float* __restrict__ bv,
            const float* __restrict__ Ws, const float* __restrict__ bgate,
            const void* __restrict__ ei)
{
    __shared__ SmemT sm;
    const int tid = threadIdx.x;
    const int nb  = blockIdx.x * TILE_N;
    const int tf  = tid & 15;
    const int tn  = tid >> 4;

    for (int idx = tid; idx < TILE_N * F_IN; idx += NTH) {
        int n = idx >> 7, k = idx & 127;
        sm.Xbuf[n * 132 + k] = x[(nb + n) * F_IN + k];
    }
    if (tid < HDIM) {
        sm.biasS[tid]       = b1[tid];
        sm.biasS[64 + tid]  = b2[tid];
        sm.biasS[128 + tid] = bk[tid];
        sm.biasS[192 + tid] = bq[tid];
        sm.biasS[256 + tid] = bv[tid];
        sm.biasS[320 + tid] = bgate[tid];
    }
    stage_w(sm.Wbuf, W1, F_IN, 0);
    __syncthreads();

    unsigned long long acc[2][2];

    // layer 1: relu(x @ W1^T + b1), K=128 in two chunks
    init_acc2(sm.biasS, 0, acc, tf);
    gemm_accum2(sm.Xbuf, 132, 0, sm.Wbuf, acc, tf, tn);
    __syncthreads();
    stage_w(sm.Wbuf, W1, F_IN, 64);
    __syncthreads();
    gemm_accum2(sm.Xbuf, 132, 64, sm.Wbuf, acc, tf, tn);
    #pragma unroll
    for (int ni = 0; ni < 2; ni++) {
        float2 a = unpk(acc[ni][0]);
        float2 b = unpk(acc[ni][1]);
        float4 v = make_float4(fmaxf(a.x, 0.f), fmaxf(a.y, 0.f),
                               fmaxf(b.x, 0.f), fmaxf(b.y, 0.f));
        *(float4*)&sm.H1buf[(tn * 2 + ni) * 68 + tf * 4] = v;
    }
    __syncthreads();

    // layer 2 -> H2 aliases Xbuf
    stage_w(sm.Wbuf, W2, HDIM, 0);
    __syncthreads();
    init_acc2(sm.biasS, 64, acc, tf);
    gemm_accum2(sm.H1buf, 68, 0, sm.Wbuf, acc, tf, tn);
    float* H2 = sm.Xbuf;
    #pragma unroll
    for (int ni = 0; ni < 2; ni++) {
        float2 a = unpk(acc[ni][0]);
        float2 b = unpk(acc[ni][1]);
        *(float4*)&H2[(tn * 2 + ni) * 68 + tf * 4] = make_float4(a.x, a.y, b.x, b.y);
    }
    __syncthreads();

    // heads: k, q, v, skip
    const float* Wh[4]   = { Wk, Wq, Wv, Ws };
    const int    boff[4] = { 128, 192, 256, 320 };
    float* outp[4]       = { g_Kf, g_Qf, g_Vf, g_Sk };
    #pragma unroll 1
    for (int h = 0; h < 4; h++) {
        stage_w(sm.Wbuf, Wh[h], HDIM, 0);
        __syncthreads();
        init_acc2(sm.biasS, boff[h], acc, tf);
        gemm_accum2(H2, 68, 0, sm.Wbuf, acc, tf, tn);
        store_head2(outp[h], nb, tf, tn, acc);
        __syncthreads();
    }

    // fused histogram tail: 2 edges per thread, overlaps other CTAs' compute
    int is64 = g_is64;
    int base = blockIdx.x * NTH + tid;
    #pragma unroll
    for (int r = 0; r < 2; r++) {
        int e = base + r * (NUM_TILES * NTH);
        if (e < N_EDGES) {
            int d = edge_at(ei, N_EDGES + e, is64);
            if ((unsigned)d < (unsigned)N_NODES)
                atomicAdd(&g_counts[d], 1);
        }
    }
}

// ---------------- CSR build ----------------
__global__ void zero_counts_kernel()
{
    int i = blockIdx.x * blockDim.x + threadIdx.x;
    if (i < N_NODES) g_counts[i] = 0;
}

// phase 1: per-block exclusive scan + block totals
__global__ void scan_blocks_kernel()
{
    __shared__ int wsums[32];
    const int tid  = threadIdx.x;
    const int lane = tid & 31;
    const int wid  = tid >> 5;
    int i = blockIdx.x * SCAN_BLK + tid;
    int v = (i < N_NODES) ? g_counts[i] : 0;
    int s = v;
    #pragma unroll
    for (int o = 1; o < 32; o <<= 1) {
        int t = __shfl_up_sync(0xffffffffu, s, o);
        if (lane >= o) s += t;
    }
    if (lane == 31) wsums[wid] = s;
    __syncthreads();
    if (wid == 0) {
        int ws = wsums[lane];
        #pragma unroll
        for (int o = 1; o < 32; o <<= 1) {
            int t = __shfl_up_sync(0xffffffffu, ws, o);
            if (lane >= o) ws += t;
        }
        wsums[lane] = ws;
    }
    __syncthreads();
    int off = (wid > 0) ? wsums[wid - 1] : 0;
    int excl = s - v + off;
    if (i < N_NODES) g_rowstart[i] = excl;
    if (tid == SCAN_BLK - 1) g_blocksums[blockIdx.x] = excl + v;
}

// phase 2: scan the 98 block totals (one small block)
__global__ void scan_sums_kernel()
{
    __shared__ int w4[4];
    const int tid  = threadIdx.x;     // 128 threads
    const int lane = tid & 31;
    const int wid  = tid >> 5;
    int v = (tid < NBLK) ? g_blocksums[tid] : 0;
    int s = v;
    #pragma unroll
    for (int o = 1; o < 32; o <<= 1) {
        int t = __shfl_up_sync(0xffffffffu, s, o);
        if (lane >= o) s += t;
    }
    if (lane == 31) w4[wid] = s;
    __syncthreads();
    int off = 0;
    #pragma unroll
    for (int w = 0; w < 4; w++) if (w < wid) off += w4[w];
    int incl = s + off;
    if (tid < NBLK) g_blockoffs[tid] = incl - v;
    if (tid == NBLK - 1) g_rowstart[N_NODES] = incl;
}

// phase 3: add offsets, produce final rowstart + cursor
__global__ void add_offsets_kernel()
{
    int i = blockIdx.x * SCAN_BLK + threadIdx.x;
    if (i < N_NODES) {
        int r = g_rowstart[i] + g_blockoffs[blockIdx.x];
        g_rowstart[i] = r;
        g_cursor[i]   = r;
    }
}

__global__ void scatter_kernel(const void* __restrict__ ei)
{
    int e = blockIdx.x * blockDim.x + threadIdx.x;
    if (e < N_EDGES) {
        int is64 = g_is64;
        int s = edge_at(ei, e, is64);
        int d = edge_at(ei, N_EDGES + e, is64);
        if ((unsigned)d < (unsigned)N_NODES && (unsigned)s < (unsigned)N_NODES) {
            int pos = atomicAdd(&g_cursor[d], 1);
            if ((unsigned)pos < (unsigned)N_EDGES)
                g_sorted_src[pos] = s;
        }
    }
}

// ---------------- aggregate + fused scorer: 2 nodes per warp, float4 per lane ----------------
__device__ __forceinline__ float sigf(float g)
{
    return __fdividef(1.0f, 1.0f + __expf(-g));
}

__global__ void aggregate_kernel(const float* __restrict__ Wsc,
                                 const float* __restrict__ bsc,
                                 float* __restrict__ score)
{
    int gwarp = (blockIdx.x * blockDim.x + threadIdx.x) >> 5;
    int lane  = threadIdx.x & 31;
    int half  = lane >> 4;
    int hl    = lane & 15;
    int i = gwarp * 2 + half;
    if (i >= N_NODES) return;
    unsigned hmask = half ? 0xffff0000u : 0x0000ffffu;

    float4 kv = *(const float4*)&g_Kf[i * HDIM + hl * 4];
    float ax = 0.f, ay = 0.f, az = 0.f, aw = 0.f;

    int start = g_rowstart[i];
    int end   = g_rowstart[i + 1];
    for (int b = start; b < end; b += 16) {
        int m = end - b; if (m > 16) m = 16;
        int j = 0;
        if (hl < m) j = g_sorted_src[b + hl];
        for (int t = 0; t < m; t++) {
            int jj = __shfl_sync(hmask, j, half * 16 + t);
            float4 q = *(const float4*)&g_Qf[jj * HDIM + hl * 4];
            float4 v = *(const float4*)&g_Vf[jj * HDIM + hl * 4];
            ax += sigf(kv.x + q.x) * v.x;
            ay += sigf(kv.y + q.y) * v.y;
            az += sigf(kv.z + q.z) * v.z;
            aw += sigf(kv.w + q.w) * v.w;
        }
    }

    float4 sk = *(const float4*)&g_Sk[i * HDIM + hl * 4];
    ax += sk.x; ay += sk.y; az += sk.z; aw += sk.w;

    float4 w = *(const float4*)&Wsc[hl * 4];
    float p = ax * w.x + ay * w.y + az * w.z + aw * w.w;
    #pragma unroll
    for (int o = 8; o > 0; o >>= 1) p += __shfl_down_sync(hmask, p, o, 16);
    if (hl == 0) score[i] = p + bsc[0];
}

// ---------------- launch (kernel launches ONLY) ----------------
extern "C" void kernel_launch(void* const* d_in, const int* in_sizes, int n_in,
                              void* d_out, int out_size)
{
    const float* x     = (const float*)d_in[0];
    const void*  ei    = d_in[1];
    const float* W1    = (const float*)d_in[2];
    const float* b1    = (const float*)d_in[3];
    const float* W2    = (const float*)d_in[4];
    const float* b2    = (const float*)d_in[5];
    const float* Wk    = (const float*)d_in[6];
    const float* bk    = (const float*)d_in[7];
    const float* Wq    = (const float*)d_in[8];
    const float* bq    = (const float*)d_in[9];
    const float* Wv    = (const float*)d_in[10];
    const float* bv    = (const float*)d_in[11];
    const float* Ws    = (const float*)d_in[12];
    const float* bgate = (const float*)d_in[13];
    const float* Wsc   = (const float*)d_in[14];
    const float* bsc   = (const float*)d_in[15];
    float* score = (float*)d_out;

    detect_dtype_kernel<<<1, 32>>>(ei);
    zero_counts_kernel<<<(N_NODES + 255) / 256, 256>>>();

    // dense node phase + fused edge histogram
    node_kernel<<<NUM_TILES, NTH>>>(x, W1, b1, W2, b2, Wk, bk,
                                    Wq, bq, Wv, bv, Ws, bgate, ei);

    scan_blocks_kernel<<<NBLK, SCAN_BLK>>>();
    scan_sums_kernel<<<1, 128>>>();
    add_offsets_kernel<<<NBLK, SCAN_BLK>>>();
    scatter_kernel<<<(N_EDGES + 255) / 256, 256>>>(ei);

    int agg_blocks = (N_NODES / 2 * 32) / 256;   // 6250, exact
    aggregate_kernel<<<agg_blocks, 256>>>(Wsc, bsc, score);
}

// round 9
// speedup vs baseline: 1.4763x; 1.2360x over previous
#include <cuda_runtime.h>
#include <cuda_fp16.h>
#include <cstdint>

#define N_NODES 100000
#define N_EDGES 1600000
#define F_IN    128
#define HDIM    64
#define TILE_N  32
#define NTH     256
#define NUM_TILES (N_NODES / TILE_N)   // 3125, exact
#define SCAN_BLK 1024
#define NBLK ((N_NODES + SCAN_BLK - 1) / SCAN_BLK)   // 98

// ---------------- device scratch (static: no allocation allowed) ----------------
__device__ float  g_Kf[N_NODES * HDIM];
__device__ __half g_Qh[N_NODES * HDIM];
__device__ __half g_Vh[N_NODES * HDIM];
__device__ float  g_Sk[N_NODES * HDIM];
__device__ int    g_counts[N_NODES];
__device__ int    g_rowstart[N_NODES + 1];
__device__ int    g_cursor[N_NODES];
__device__ int    g_sorted_src[N_EDGES];
__device__ int    g_blocksums[128];
__device__ int    g_blockoffs[128];
__device__ int    g_is64;

// ---------------- f32x2 packed helpers ----------------
__device__ __forceinline__ unsigned long long pack2(float v) {
    unsigned long long r; unsigned u = __float_as_uint(v);
    asm("mov.b64 %0, {%1, %1};" : "=l"(r) : "r"(u));
    return r;
}
__device__ __forceinline__ unsigned long long pk2(float lo, float hi) {
    unsigned long long r;
    asm("mov.b64 %0, {%1, %2};" : "=l"(r) : "r"(__float_as_uint(lo)), "r"(__float_as_uint(hi)));
    return r;
}
__device__ __forceinline__ float2 unpk(unsigned long long v) {
    unsigned lo, hi;
    asm("mov.b64 {%0, %1}, %2;" : "=r"(lo), "=r"(hi) : "l"(v));
    return make_float2(__uint_as_float(lo), __uint_as_float(hi));
}
__device__ __forceinline__ void ffma2(unsigned long long& acc,
                                      unsigned long long a, unsigned long long b) {
    asm("fma.rn.f32x2 %0, %1, %2, %0;" : "+l"(acc) : "l"(a), "l"(b));
}

// ---------------- edge dtype probe (parallel) ----------------
__global__ void detect_dtype_kernel(const void* __restrict__ ei)
{
    const unsigned long long* p = (const unsigned long long*)ei;
    int bad = (p[threadIdx.x] >> 32) != 0ull;
    bad = __syncthreads_or(bad);
    if (threadIdx.x == 0) g_is64 = !bad;
}

__device__ __forceinline__ int edge_at(const void* __restrict__ ei, int pos, int is64)
{
    if (is64) return (int)((const long long*)ei)[pos];
    return ((const int*)ei)[pos];
}

// ---------------- fused node kernel ----------------
struct SmemT {
    __align__(16) float Wbuf[64 * 68];
    __align__(16) float Xbuf[TILE_N * 132];
    __align__(16) float H1buf[TILE_N * 68];
    float biasS[6 * 64];
};

__device__ __forceinline__ void stage_w(float* __restrict__ Wbuf,
                                        const float* __restrict__ W,
                                        int ldw, int kofs)
{
    #pragma unroll
    for (int idx = threadIdx.x; idx < 64 * 64; idx += NTH) {
        int f = idx >> 6, k = idx & 63;
        Wbuf[k * 68 + f] = W[f * ldw + kofs + k];
    }
}

__device__ __forceinline__ void gemm_accum2(const float* __restrict__ In, int ldin, int kbase,
                                            const float* __restrict__ Wbuf,
                                            unsigned long long acc[2][2], int tf, int tn)
{
    const float* in0 = In + (tn * 2 + 0) * ldin + kbase;
    const float* in1 = In + (tn * 2 + 1) * ldin + kbase;
    #pragma unroll 8
    for (int k = 0; k < 64; k++) {
        const ulonglong2 w = *(const ulonglong2*)&Wbuf[k * 68 + tf * 4];
        unsigned long long x0 = pack2(in0[k]);
        unsigned long long x1 = pack2(in1[k]);
        ffma2(acc[0][0], x0, w.x); ffma2(acc[0][1], x0, w.y);
        ffma2(acc[1][0], x1, w.x); ffma2(acc[1][1], x1, w.y);
    }
}

__device__ __forceinline__ void init_acc2(const float* __restrict__ biasS, int boff,
                                          unsigned long long acc[2][2], int tf)
{
    unsigned long long p0 = pk2(biasS[boff + tf * 4 + 0], biasS[boff + tf * 4 + 1]);
    unsigned long long p1 = pk2(biasS[boff + tf * 4 + 2], biasS[boff + tf * 4 + 3]);
    acc[0][0] = p0; acc[0][1] = p1;
    acc[1][0] = p0; acc[1][1] = p1;
}

__device__ __forceinline__ void store_head_f32(float* __restrict__ out, int nb,
                                               int tf, int tn, unsigned long long acc[2][2])
{
    #pragma unroll
    for (int ni = 0; ni < 2; ni++) {
        int node = nb + tn * 2 + ni;
        float2 a = unpk(acc[ni][0]);
        float2 b = unpk(acc[ni][1]);
        *(float4*)&out[node * HDIM + tf * 4] = make_float4(a.x, a.y, b.x, b.y);
    }
}

__device__ __forceinline__ void store_head_f16(__half* __restrict__ out, int nb,
                                               int tf, int tn, unsigned long long acc[2][2])
{
    #pragma unroll
    for (int ni = 0; ni < 2; ni++) {
        int node = nb + tn * 2 + ni;
        float2 a = unpk(acc[ni][0]);
        float2 b = unpk(acc[ni][1]);
        __half2 h0 = __floats2half2_rn(a.x, a.y);
        __half2 h1 = __floats2half2_rn(b.x, b.y);
        uint2 pk;
        pk.x = *(unsigned*)&h0;
        pk.y = *(unsigned*)&h1;
        *(uint2*)&out[node * HDIM + tf * 4] = pk;
    }
}

__global__ void __launch_bounds__(NTH)
node_kernel(const float* __restrict__ x,
            const float* __restrict__ W1, const float* __restrict__ b1,
            const float* __restrict__ W2, const float* __restrict__ b2,
            const float* __restrict__ Wk, const float* __restrict__ bk,
            const float* __restrict__ Wq, const float* __restrict__ bq,
            const float* __restrict__ Wv, const float* __restrict__ bv,
            const float* __restrict__ Ws, const float* __restrict__ bgate,
            const void* __restrict__ ei)
{
    __shared__ SmemT sm;
    const int tid = threadIdx.x;
    const int nb  = blockIdx.x * TILE_N;
    const int tf  = tid & 15;
    const int tn  = tid >> 4;

    for (int idx = tid; idx < TILE_N * F_IN; idx += NTH) {
        int n = idx >> 7, k = idx & 127;
        sm.Xbuf[n * 132 + k] = x[(nb + n) * F_IN + k];
    }
    if (tid < HDIM) {
        sm.biasS[tid]       = b1[tid];
        sm.biasS[64 + tid]  = b2[tid];
        sm.biasS[128 + tid] = bk[tid];
        sm.biasS[192 + tid] = bq[tid];
        sm.biasS[256 + tid] = bv[tid];
        sm.biasS[320 + tid] = bgate[tid];
    }
    stage_w(sm.Wbuf, W1, F_IN, 0);
    __syncthreads();

    unsigned long long acc[2][2];

    // layer 1: relu(x @ W1^T + b1), K=128 in two chunks
    init_acc2(sm.biasS, 0, acc, tf);
    gemm_accum2(sm.Xbuf, 132, 0, sm.Wbuf, acc, tf, tn);
    __syncthreads();
    stage_w(sm.Wbuf, W1, F_IN, 64);
    __syncthreads();
    gemm_accum2(sm.Xbuf, 132, 64, sm.Wbuf, acc, tf, tn);
    #pragma unroll
    for (int ni = 0; ni < 2; ni++) {
        float2 a = unpk(acc[ni][0]);
        float2 b = unpk(acc[ni][1]);
        float4 v = make_float4(fmaxf(a.x, 0.f), fmaxf(a.y, 0.f),
                               fmaxf(b.x, 0.f), fmaxf(b.y, 0.f));
        *(float4*)&sm.H1buf[(tn * 2 + ni) * 68 + tf * 4] = v;
    }
    __syncthreads();

    // layer 2 -> H2 aliases Xbuf
    stage_w(sm.Wbuf, W2, HDIM, 0);
    __syncthreads();
    init_acc2(sm.biasS, 64, acc, tf);
    gemm_accum2(sm.H1buf, 68, 0, sm.Wbuf, acc, tf, tn);
    float* H2 = sm.Xbuf;
    #pragma unroll
    for (int ni = 0; ni < 2; ni++) {
        float2 a = unpk(acc[ni][0]);
        float2 b = unpk(acc[ni][1]);
        *(float4*)&H2[(tn * 2 + ni) * 68 + tf * 4] = make_float4(a.x, a.y, b.x, b.y);
    }
    __syncthreads();

    // heads: k (fp32), q (fp16), v (fp16), skip (fp32)
    stage_w(sm.Wbuf, Wk, HDIM, 0);
    __syncthreads();
    init_acc2(sm.biasS, 128, acc, tf);
    gemm_accum2(H2, 68, 0, sm.Wbuf, acc, tf, tn);
    store_head_f32(g_Kf, nb, tf, tn, acc);
    __syncthreads();

    stage_w(sm.Wbuf, Wq, HDIM, 0);
    __syncthreads();
    init_acc2(sm.biasS, 192, acc, tf);
    gemm_accum2(H2, 68, 0, sm.Wbuf, acc, tf, tn);
    store_head_f16(g_Qh, nb, tf, tn, acc);
    __syncthreads();

    stage_w(sm.Wbuf, Wv, HDIM, 0);
    __syncthreads();
    init_acc2(sm.biasS, 256, acc, tf);
    gemm_accum2(H2, 68, 0, sm.Wbuf, acc, tf, tn);
    store_head_f16(g_Vh, nb, tf, tn, acc);
    __syncthreads();

    stage_w(sm.Wbuf, Ws, HDIM, 0);
    __syncthreads();
    init_acc2(sm.biasS, 320, acc, tf);
    gemm_accum2(H2, 68, 0, sm.Wbuf, acc, tf, tn);
    store_head_f32(g_Sk, nb, tf, tn, acc);

    // fused histogram tail: 2 edges per thread, overlaps other CTAs' compute
    int is64 = g_is64;
    int base = blockIdx.x * NTH + tid;
    #pragma unroll
    for (int r = 0; r < 2; r++) {
        int e = base + r * (NUM_TILES * NTH);
        if (e < N_EDGES) {
            int d = edge_at(ei, N_EDGES + e, is64);
            if ((unsigned)d < (unsigned)N_NODES)
                atomicAdd(&g_counts[d], 1);
        }
    }
}

// ---------------- CSR build ----------------
__global__ void zero_counts_kernel()
{
    int i = blockIdx.x * blockDim.x + threadIdx.x;
    if (i < N_NODES) g_counts[i] = 0;
}

__global__ void scan_blocks_kernel()
{
    __shared__ int wsums[32];
    const int tid  = threadIdx.x;
    const int lane = tid & 31;
    const int wid  = tid >> 5;
    int i = blockIdx.x * SCAN_BLK + tid;
    int v = (i < N_NODES) ? g_counts[i] : 0;
    int s = v;
    #pragma unroll
    for (int o = 1; o < 32; o <<= 1) {
        int t = __shfl_up_sync(0xffffffffu, s, o);
        if (lane >= o) s += t;
    }
    if (lane == 31) wsums[wid] = s;
    __syncthreads();
    if (wid == 0) {
        int ws = wsums[lane];
        #pragma unroll
        for (int o = 1; o < 32; o <<= 1) {
            int t = __shfl_up_sync(0xffffffffu, ws, o);
            if (lane >= o) ws += t;
        }
        wsums[lane] = ws;
    }
    __syncthreads();
    int off = (wid > 0) ? wsums[wid - 1] : 0;
    int excl = s - v + off;
    if (i < N_NODES) g_rowstart[i] = excl;
    if (tid == SCAN_BLK - 1) g_blocksums[blockIdx.x] = excl + v;
}

__global__ void scan_sums_kernel()
{
    __shared__ int w4[4];
    const int tid  = threadIdx.x;
    const int lane = tid & 31;
    const int wid  = tid >> 5;
    int v = (tid < NBLK) ? g_blocksums[tid] : 0;
    int s = v;
    #pragma unroll
    for (int o = 1; o < 32; o <<= 1) {
        int t = __shfl_up_sync(0xffffffffu, s, o);
        if (lane >= o) s += t;
    }
    if (lane == 31) w4[wid] = s;
    __syncthreads();
    int off = 0;
    #pragma unroll
    for (int w = 0; w < 4; w++) if (w < wid) off += w4[w];
    int incl = s + off;
    if (tid < NBLK) g_blockoffs[tid] = incl - v;
    if (tid == NBLK - 1) g_rowstart[N_NODES] = incl;
}

__global__ void add_offsets_kernel()
{
    int i = blockIdx.x * SCAN_BLK + threadIdx.x;
    if (i < N_NODES) {
        int r = g_rowstart[i] + g_blockoffs[blockIdx.x];
        g_rowstart[i] = r;
        g_cursor[i]   = r;
    }
}

__global__ void scatter_kernel(const void* __restrict__ ei)
{
    int e = blockIdx.x * blockDim.x + threadIdx.x;
    if (e < N_EDGES) {
        int is64 = g_is64;
        int s = edge_at(ei, e, is64);
        int d = edge_at(ei, N_EDGES + e, is64);
        if ((unsigned)d < (unsigned)N_NODES && (unsigned)s < (unsigned)N_NODES) {
            int pos = atomicAdd(&g_cursor[d], 1);
            if ((unsigned)pos < (unsigned)N_EDGES)
                g_sorted_src[pos] = s;
        }
    }
}

// ---------------- aggregate + fused scorer ----------------
// 2 nodes/warp (16 lanes each), fp16 q/v gathers, 4-edge software pipeline.
__device__ __forceinline__ float sigf(float g)
{
    return __fdividef(1.0f, 1.0f + __expf(-g));
}

__global__ void aggregate_kernel(const float* __restrict__ Wsc,
                                 const float* __restrict__ bsc,
                                 float* __restrict__ score)
{
    int gwarp = (blockIdx.x * blockDim.x + threadIdx.x) >> 5;
    int lane  = threadIdx.x & 31;
    int half  = lane >> 4;
    int hl    = lane & 15;
    int i = gwarp * 2 + half;
    if (i >= N_NODES) return;
    unsigned hmask = half ? 0xffff0000u : 0x0000ffffu;

    float4 kv = *(const float4*)&g_Kf[i * HDIM + hl * 4];
    float ax = 0.f, ay = 0.f, az = 0.f, aw = 0.f;

    int start = g_rowstart[i];
    int end   = g_rowstart[i + 1];
    for (int b = start; b < end; b += 16) {
        int m = end - b; if (m > 16) m = 16;
        int j = g_sorted_src[b + ((hl < m) ? hl : 0)];
        for (int t0 = 0; t0 < m; t0 += 4) {
            uint2 qr[4], vr[4];
            float msk[4];
            #pragma unroll
            for (int u = 0; u < 4; u++) {
                int t  = t0 + u;
                int tc = (t < m) ? t : (m - 1);
                int jj = __shfl_sync(hmask, j, half * 16 + tc);
                qr[u] = *(const uint2*)&g_Qh[jj * HDIM + hl * 4];
                vr[u] = *(const uint2*)&g_Vh[jj * HDIM + hl * 4];
                msk[u] = (t < m) ? 1.0f : 0.0f;
            }
            #pragma unroll
            for (int u = 0; u < 4; u++) {
                float2 q01 = __half22float2(*(const __half2*)&qr[u].x);
                float2 q23 = __half22float2(*(const __half2*)&qr[u].y);
                float2 v01 = __half22float2(*(const __half2*)&vr[u].x);
                float2 v23 = __half22float2(*(const __half2*)&vr[u].y);
                float mk = msk[u];
                ax += mk * sigf(kv.x + q01.x) * v01.x;
                ay += mk * sigf(kv.y + q01.y) * v01.y;
                az += mk * sigf(kv.z + q23.x) * v23.x;
                aw += mk * sigf(kv.w + q23.y) * v23.y;
            }
        }
    }

    float4 sk = *(const float4*)&g_Sk[i * HDIM + hl * 4];
    ax += sk.x; ay += sk.y; az += sk.z; aw += sk.w;

    float4 w = *(const float4*)&Wsc[hl * 4];
    float p = ax * w.x + ay * w.y + az * w.z + aw * w.w;
    #pragma unroll
    for (int o = 8; o > 0; o >>= 1) p += __shfl_down_sync(hmask, p, o, 16);
    if (hl == 0) score[i] = p + bsc[0];
}

// ---------------- launch (kernel launches ONLY) ----------------
extern "C" void kernel_launch(void* const* d_in, const int* in_sizes, int n_in,
                              void* d_out, int out_size)
{
    const float* x     = (const float*)d_in[0];
    const void*  ei    = d_in[1];
    const float* W1    = (const float*)d_in[2];
    const float* b1    = (const float*)d_in[3];
    const float* W2    = (const float*)d_in[4];
    const float* b2    = (const float*)d_in[5];
    const float* Wk    = (const float*)d_in[6];
    const float* bk    = (const float*)d_in[7];
    const float* Wq    = (const float*)d_in[8];
    const float* bq    = (const float*)d_in[9];
    const float* Wv    = (const float*)d_in[10];
    const float* bv    = (const float*)d_in[11];
    const float* Ws    = (const float*)d_in[12];
    const float* bgate = (const float*)d_in[13];
    const float* Wsc   = (const float*)d_in[14];
    const float* bsc   = (const float*)d_in[15];
    float* score = (float*)d_out;

    detect_dtype_kernel<<<1, 512>>>(ei);
    zero_counts_kernel<<<(N_NODES + 255) / 256, 256>>>();

    node_kernel<<<NUM_TILES, NTH>>>(x, W1, b1, W2, b2, Wk, bk,
                                    Wq, bq, Wv, bv, Ws, bgate, ei);

    scan_blocks_kernel<<<NBLK, SCAN_BLK>>>();
    scan_sums_kernel<<<1, 128>>>();
    add_offsets_kernel<<<NBLK, SCAN_BLK>>>();
    scatter_kernel<<<(N_EDGES + 255) / 256, 256>>>(ei);

    int agg_blocks = (N_NODES / 2 * 32) / 256;   // 6250, exact
    aggregate_kernel<<<agg_blocks, 256>>>(Wsc, bsc, score);
}

// round 11
// speedup vs baseline: 1.6502x; 1.1178x over previous
#include <cuda_runtime.h>
#include <cuda_fp16.h>
#include <cstdint>

#define N_NODES 100000
#define N_EDGES 1600000
#define F_IN    128
#define HDIM    64
#define TILE_N  32
#define NTH     256
#define NUM_TILES (N_NODES / TILE_N)   // 3125, exact
#define SCAN_BLK 1024
#define NBLK ((N_NODES + SCAN_BLK - 1) / SCAN_BLK)   // 98
#define WSTR 66                        // Wbuf row stride (words): even + 16-distinct banks

// ---------------- device scratch (static: no allocation allowed) ----------------
__device__ float  g_Kf[N_NODES * HDIM];
__device__ __half g_Qh[N_NODES * HDIM];
__device__ __half g_Vh[N_NODES * HDIM];
__device__ float  g_Sk[N_NODES * HDIM];
__device__ int    g_counts[N_NODES];
__device__ int    g_rowstart[N_NODES + 1];
__device__ int    g_cursor[N_NODES];
__device__ int    g_sorted_src[N_EDGES];
__device__ int    g_blocksums[128];
__device__ int    g_blockoffs[128];
__device__ int    g_is64;

// ---------------- f32x2 packed helpers ----------------
__device__ __forceinline__ unsigned long long pk2(float lo, float hi) {
    unsigned long long r;
    asm("mov.b64 %0, {%1, %2};" : "=l"(r) : "r"(__float_as_uint(lo)), "r"(__float_as_uint(hi)));
    return r;
}
__device__ __forceinline__ float2 unpk(unsigned long long v) {
    unsigned lo, hi;
    asm("mov.b64 {%0, %1}, %2;" : "=r"(lo), "=r"(hi) : "l"(v));
    return make_float2(__uint_as_float(lo), __uint_as_float(hi));
}
__device__ __forceinline__ void ffma2(unsigned long long& acc,
                                      unsigned long long a, unsigned long long b) {
    asm("fma.rn.f32x2 %0, %1, %2, %0;" : "+l"(acc) : "l"(a), "l"(b));
}

// ---------------- edge dtype probe (parallel) ----------------
__global__ void detect_dtype_kernel(const void* __restrict__ ei)
{
    const unsigned long long* p = (const unsigned long long*)ei;
    int bad = (p[threadIdx.x] >> 32) != 0ull;
    bad = __syncthreads_or(bad);
    if (threadIdx.x == 0) g_is64 = !bad;
}

__device__ __forceinline__ int edge_at(const void* __restrict__ ei, int pos, int is64)
{
    if (is64) return (int)((const long long*)ei)[pos];
    return ((const int*)ei)[pos];
}

// ---------------- fused node kernel ----------------
// Wbuf: f-row-major, row index permuted: f=(tf*4+fi) stored at row (fi*16+tf).
// K-pair packing: both FFMA2 operands are adjacent-k pairs -> LDS.64, no MOVs.
struct SmemT {
    __align__(16) float Wbuf[64 * WSTR];     // 16896 B
    __align__(16) float Xbuf[TILE_N * 132];  // 16896 B (reused as H2)
    __align__(16) float H1buf[TILE_N * 68];  // 8704 B
    float biasS[6 * 64];                     // 1536 B
};                                           // total 44032 B < 48K static

__device__ __forceinline__ void stage_w(float* __restrict__ Wbuf,
                                        const float* __restrict__ W,
                                        int ldw, int kofs)
{
    #pragma unroll
    for (int idx = threadIdx.x; idx < 64 * 64; idx += NTH) {
        int f = idx >> 6, k = idx & 63;
        int row = ((f & 3) << 4) | (f >> 2);       // fi*16 + tf
        Wbuf[row * WSTR + k] = W[f * ldw + kofs + k];
    }
}

// acc[node 0..1][feat 0..3]: each holds (sum over even k, sum over odd k)
__device__ __forceinline__ void gemm_kp(const float* __restrict__ In, int ldin, int kbase,
                                        const float* __restrict__ Wbuf,
                                        unsigned long long acc[2][4], int tf, int tn)
{
    const float* in0 = In + (tn * 2 + 0) * ldin + kbase;
    const float* in1 = In + (tn * 2 + 1) * ldin + kbase;
    const float* w0 = Wbuf + (0 * 16 + tf) * WSTR;   // fi=0
    const float* w1 = Wbuf + (1 * 16 + tf) * WSTR;   // fi=1
    const float* w2 = Wbuf + (2 * 16 + tf) * WSTR;   // fi=2
    const float* w3 = Wbuf + (3 * 16 + tf) * WSTR;   // fi=3
    #pragma unroll 8
    for (int kp = 0; kp < 32; kp++) {
        unsigned long long xp0 = *(const unsigned long long*)&in0[kp * 2];
        unsigned long long xp1 = *(const unsigned long long*)&in1[kp * 2];
        unsigned long long wa = *(const unsigned long long*)&w0[kp * 2];
        unsigned long long wb = *(const unsigned long long*)&w1[kp * 2];
        unsigned long long wc = *(const unsigned long long*)&w2[kp * 2];
        unsigned long long wd = *(const unsigned long long*)&w3[kp * 2];
        ffma2(acc[0][0], xp0, wa); ffma2(acc[0][1], xp0, wb);
        ffma2(acc[0][2], xp0, wc); ffma2(acc[0][3], xp0, wd);
        ffma2(acc[1][0], xp1, wa); ffma2(acc[1][1], xp1, wb);
        ffma2(acc[1][2], xp1, wc); ffma2(acc[1][3], xp1, wd);
    }
}

__device__ __forceinline__ void init_kp(const float* __restrict__ biasS, int boff,
                                        unsigned long long acc[2][4], int tf)
{
    #pragma unroll
    for (int fi = 0; fi < 4; fi++) {
        unsigned long long b = pk2(biasS[boff + tf * 4 + fi], 0.0f);
        acc[0][fi] = b; acc[1][fi] = b;
    }
}

__device__ __forceinline__ void reduce_kp(unsigned long long acc[2][4], float r[2][4])
{
    #pragma unroll
    for (int ni = 0; ni < 2; ni++)
        #pragma unroll
        for (int fi = 0; fi < 4; fi++) {
            float2 p = unpk(acc[ni][fi]);
            r[ni][fi] = p.x + p.y;
        }
}

__global__ void __launch_bounds__(NTH)
node_kernel(const float* __restrict__ x,
            const float* __restrict__ W1, const float* __restrict__ b1,
            const float* __restrict__ W2, const float* __restrict__ b2,
            const float* __restrict__ Wk, const float* __restrict__ bk,
            const float* __restrict__ Wq, const float* __restrict__ bq,
            const float* __restrict__ Wv, const float* __restrict__ bv,
            const float* __restrict__ Ws, const float* __restrict__ bgate,
            const void* __restrict__ ei)
{
    __shared__ SmemT sm;
    const int tid = threadIdx.x;
    const int nb  = blockIdx.x * TILE_N;
    const int tf  = tid & 15;
    const int tn  = tid >> 4;

    for (int idx = tid; idx < TILE_N * F_IN; idx += NTH) {
        int n = idx >> 7, k = idx & 127;
        sm.Xbuf[n * 132 + k] = x[(nb + n) * F_IN + k];
    }
    if (tid < HDIM) {
        sm.biasS[tid]       = b1[tid];
        sm.biasS[64 + tid]  = b2[tid];
        sm.biasS[128 + tid] = bk[tid];
        sm.biasS[192 + tid] = bq[tid];
        sm.biasS[256 + tid] = bv[tid];
        sm.biasS[320 + tid] = bgate[tid];
    }
    stage_w(sm.Wbuf, W1, F_IN, 0);
    __syncthreads();

    unsigned long long acc[2][4];
    float r[2][4];

    // layer 1: relu(x @ W1^T + b1), K=128 in two chunks
    init_kp(sm.biasS, 0, acc, tf);
    gemm_kp(sm.Xbuf, 132, 0, sm.Wbuf, acc, tf, tn);
    __syncthreads();
    stage_w(sm.Wbuf, W1, F_IN, 64);
    __syncthreads();
    gemm_kp(sm.Xbuf, 132, 64, sm.Wbuf, acc, tf, tn);
    reduce_kp(acc, r);
    #pragma unroll
    for (int ni = 0; ni < 2; ni++) {
        float4 v = make_float4(fmaxf(r[ni][0], 0.f), fmaxf(r[ni][1], 0.f),
                               fmaxf(r[ni][2], 0.f), fmaxf(r[ni][3], 0.f));
        *(float4*)&sm.H1buf[(tn * 2 + ni) * 68 + tf * 4] = v;
    }
    __syncthreads();

    // layer 2 -> H2 aliases Xbuf (stride 132)
    stage_w(sm.Wbuf, W2, HDIM, 0);
    __syncthreads();
    init_kp(sm.biasS, 64, acc, tf);
    gemm_kp(sm.H1buf, 68, 0, sm.Wbuf, acc, tf, tn);
    reduce_kp(acc, r);
    float* H2 = sm.Xbuf;
    #pragma unroll
    for (int ni = 0; ni < 2; ni++)
        *(float4*)&H2[(tn * 2 + ni) * 132 + tf * 4] =
            make_float4(r[ni][0], r[ni][1], r[ni][2], r[ni][3]);
    __syncthreads();

    // ---- heads ----
    // k (fp32)
    stage_w(sm.Wbuf, Wk, HDIM, 0);
    __syncthreads();
    init_kp(sm.biasS, 128, acc, tf);
    gemm_kp(H2, 132, 0, sm.Wbuf, acc, tf, tn);
    reduce_kp(acc, r);
    #pragma unroll
    for (int ni = 0; ni < 2; ni++)
        *(float4*)&g_Kf[(nb + tn * 2 + ni) * HDIM + tf * 4] =
            make_float4(r[ni][0], r[ni][1], r[ni][2], r[ni][3]);
    __syncthreads();

    // q (fp16)
    stage_w(sm.Wbuf, Wq, HDIM, 0);
    __syncthreads();
    init_kp(sm.biasS, 192, acc, tf);
    gemm_kp(H2, 132, 0, sm.Wbuf, acc, tf, tn);
    reduce_kp(acc, r);
    #pragma unroll
    for (int ni = 0; ni < 2; ni++) {
        __half2 h0 = __floats2half2_rn(r[ni][0], r[ni][1]);
        __half2 h1 = __floats2half2_rn(r[ni][2], r[ni][3]);
        uint2 pk; pk.x = *(unsigned*)&h0; pk.y = *(unsigned*)&h1;
        *(uint2*)&g_Qh[(nb + tn * 2 + ni) * HDIM + tf * 4] = pk;
    }
    __syncthreads();

    // v (fp16)
    stage_w(sm.Wbuf, Wv, HDIM, 0);
    __syncthreads();
    init_kp(sm.biasS, 256, acc, tf);
    gemm_kp(H2, 132, 0, sm.Wbuf, acc, tf, tn);
    reduce_kp(acc, r);
    #pragma unroll
    for (int ni = 0; ni < 2; ni++) {
        __half2 h0 = __floats2half2_rn(r[ni][0], r[ni][1]);
        __half2 h1 = __floats2half2_rn(r[ni][2], r[ni][3]);
        uint2 pk; pk.x = *(unsigned*)&h0; pk.y = *(unsigned*)&h1;
        *(uint2*)&g_Vh[(nb + tn * 2 + ni) * HDIM + tf * 4] = pk;
    }
    __syncthreads();

    // skip (fp32)
    stage_w(sm.Wbuf, Ws, HDIM, 0);
    __syncthreads();
    init_kp(sm.biasS, 320, acc, tf);
    gemm_kp(H2, 132, 0, sm.Wbuf, acc, tf, tn);
    reduce_kp(acc, r);
    #pragma unroll
    for (int ni = 0; ni < 2; ni++)
        *(float4*)&g_Sk[(nb + tn * 2 + ni) * HDIM + tf * 4] =
            make_float4(r[ni][0], r[ni][1], r[ni][2], r[ni][3]);

    // fused histogram tail: 2 edges per thread, overlaps other CTAs' compute
    int is64 = g_is64;
    int base = blockIdx.x * NTH + tid;
    #pragma unroll
    for (int rr = 0; rr < 2; rr++) {
        int e = base + rr * (NUM_TILES * NTH);
        if (e < N_EDGES) {
            int d = edge_at(ei, N_EDGES + e, is64);
            if ((unsigned)d < (unsigned)N_NODES)
                atomicAdd(&g_counts[d], 1);
        }
    }
}

// ---------------- CSR build ----------------
__global__ void zero_counts_kernel()
{
    int i = blockIdx.x * blockDim.x + threadIdx.x;
    if (i < N_NODES) g_counts[i] = 0;
}

__global__ void scan_blocks_kernel()
{
    __shared__ int wsums[32];
    const int tid  = threadIdx.x;
    const int lane = tid & 31;
    const int wid  = tid >> 5;
    int i = blockIdx.x * SCAN_BLK + tid;
    int v = (i < N_NODES) ? g_counts[i] : 0;
    int s = v;
    #pragma unroll
    for (int o = 1; o < 32; o <<= 1) {
        int t = __shfl_up_sync(0xffffffffu, s, o);
        if (lane >= o) s += t;
    }
    if (lane == 31) wsums[wid] = s;
    __syncthreads();
    if (wid == 0) {
        int ws = wsums[lane];
        #pragma unroll
        for (int o = 1; o < 32; o <<= 1) {
            int t = __shfl_up_sync(0xffffffffu, ws, o);
            if (lane >= o) ws += t;
        }
        wsums[lane] = ws;
    }
    __syncthreads();
    int off = (wid > 0) ? wsums[wid - 1] : 0;
    int excl = s - v + off;
    if (i < N_NODES) g_rowstart[i] = excl;
    if (tid == SCAN_BLK - 1) g_blocksums[blockIdx.x] = excl + v;
}

__global__ void scan_sums_kernel()
{
    __shared__ int w4[4];
    const int tid  = threadIdx.x;
    const int lane = tid & 31;
    const int wid  = tid >> 5;
    int v = (tid < NBLK) ? g_blocksums[tid] : 0;
    int s = v;
    #pragma unroll
    for (int o = 1; o < 32; o <<= 1) {
        int t = __shfl_up_sync(0xffffffffu, s, o);
        if (lane >= o) s += t;
    }
    if (lane == 31) w4[wid] = s;
    __syncthreads();
    int off = 0;
    #pragma unroll
    for (int w = 0; w < 4; w++) if (w < wid) off += w4[w];
    int incl = s + off;
    if (tid < NBLK) g_blockoffs[tid] = incl - v;
    if (tid == NBLK - 1) g_rowstart[N_NODES] = incl;
}

__global__ void add_offsets_kernel()
{
    int i = blockIdx.x * SCAN_BLK + threadIdx.x;
    if (i < N_NODES) {
        int r = g_rowstart[i] + g_blockoffs[blockIdx.x];
        g_rowstart[i] = r;
        g_cursor[i]   = r;
    }
}

__global__ void scatter_kernel(const void* __restrict__ ei)
{
    int e = blockIdx.x * blockDim.x + threadIdx.x;
    if (e < N_EDGES) {
        int is64 = g_is64;
        int s = edge_at(ei, e, is64);
        int d = edge_at(ei, N_EDGES + e, is64);
        if ((unsigned)d < (unsigned)N_NODES && (unsigned)s < (unsigned)N_NODES) {
            int pos = atomicAdd(&g_cursor[d], 1);
            if ((unsigned)pos < (unsigned)N_EDGES)
                g_sorted_src[pos] = s;
        }
    }
}

// ---------------- aggregate + fused scorer ----------------
// sigmoid(k+q) = 0.5*tanh(0.5k + 0.5q) + 0.5  -> 1 MUFU.TANH + 2 FFMA-imm
__device__ __forceinline__ float gatef(float q, float kh)
{
    float t;
    asm("tanh.approx.f32 %0, %1;" : "=f"(t) : "f"(fmaf(q, 0.5f, kh)));
    return fmaf(t, 0.5f, 0.5f);
}

__global__ void aggregate_kernel(const float* __restrict__ Wsc,
                                 const float* __restrict__ bsc,
                                 float* __restrict__ score)
{
    int gwarp = (blockIdx.x * blockDim.x + threadIdx.x) >> 5;
    int lane  = threadIdx.x & 31;
    int half  = lane >> 4;
    int hl    = lane & 15;
    int i = gwarp * 2 + half;
    if (i >= N_NODES) return;
    unsigned hmask = half ? 0xffff0000u : 0x0000ffffu;

    float4 kh = *(const float4*)&g_Kf[i * HDIM + hl * 4];
    kh.x *= 0.5f; kh.y *= 0.5f; kh.z *= 0.5f; kh.w *= 0.5f;
    float ax = 0.f, ay = 0.f, az = 0.f, aw = 0.f;

    int start = g_rowstart[i];
    int end   = g_rowstart[i + 1];
    for (int b = start; b < end; b += 16) {
        int m = end - b; if (m > 16) m = 16;
        int j = g_sorted_src[b + ((hl < m) ? hl : 0)];
        for (int t0 = 0; t0 < m; t0 += 4) {
            uint2 qr[4], vr[4];
            #pragma unroll
            for (int u = 0; u < 4; u++) {
                int t  = t0 + u;
                int tc = (t < m) ? t : 0;
                int jj = __shfl_sync(hmask, j, half * 16 + tc);
                qr[u] = *(const uint2*)&g_Qh[jj * HDIM + hl * 4];
                vr[u] = *(const uint2*)&g_Vh[jj * HDIM + hl * 4];
                if (t >= m) { vr[u].x = 0u; vr[u].y = 0u; }   // v=0 kills the lane's term
            }
            #pragma unroll
            for (int u = 0; u < 4; u++) {
                float2 q01 = __half22float2(*(const __half2*)&qr[u].x);
                float2 q23 = __half22float2(*(const __half2*)&qr[u].y);
                float2 v01 = __half22float2(*(const __half2*)&vr[u].x);
                float2 v23 = __half22float2(*(const __half2*)&vr[u].y);
                ax = fmaf(gatef(q01.x, kh.x), v01.x, ax);
                ay = fmaf(gatef(q01.y, kh.y), v01.y, ay);
                az = fmaf(gatef(q23.x, kh.z), v23.x, az);
                aw = fmaf(gatef(q23.y, kh.w), v23.y, aw);
            }
        }
    }

    float4 sk = *(const float4*)&g_Sk[i * HDIM + hl * 4];
    ax += sk.x; ay += sk.y; az += sk.z; aw += sk.w;

    float4 w = *(const float4*)&Wsc[hl * 4];
    float p = ax * w.x + ay * w.y + az * w.z + aw * w.w;
    #pragma unroll
    for (int o = 8; o > 0; o >>= 1) p += __shfl_down_sync(hmask, p, o, 16);
    if (hl == 0) score[i] = p + bsc[0];
}

// ---------------- launch (kernel launches ONLY) ----------------
extern "C" void kernel_launch(void* const* d_in, const int* in_sizes, int n_in,
                              void* d_out, int out_size)
{
    const float* x     = (const float*)d_in[0];
    const void*  ei    = d_in[1];
    const float* W1    = (const float*)d_in[2];
    const float* b1    = (const float*)d_in[3];
    const float* W2    = (const float*)d_in[4];
    const float* b2    = (const float*)d_in[5];
    const float* Wk    = (const float*)d_in[6];
    const float* bk    = (const float*)d_in[7];
    const float* Wq    = (const float*)d_in[8];
    const float* bq    = (const float*)d_in[9];
    const float* Wv    = (const float*)d_in[10];
    const float* bv    = (const float*)d_in[11];
    const float* Ws    = (const float*)d_in[12];
    const float* bgate = (const float*)d_in[13];
    const float* Wsc   = (const float*)d_in[14];
    const float* bsc   = (const float*)d_in[15];
    float* score = (float*)d_out;

    detect_dtype_kernel<<<1, 512>>>(ei);
    zero_counts_kernel<<<(N_NODES + 255) / 256, 256>>>();

    node_kernel<<<NUM_TILES, NTH>>>(x, W1, b1, W2, b2, Wk, bk,
                                    Wq, bq, Wv, bv, Ws, bgate, ei);

    scan_blocks_kernel<<<NBLK, SCAN_BLK>>>();
    scan_sums_kernel<<<1, 128>>>();
    add_offsets_kernel<<<NBLK, SCAN_BLK>>>();
    scatter_kernel<<<(N_EDGES + 255) / 256, 256>>>(ei);

    int agg_blocks = (N_NODES / 2 * 32) / 256;   // 6250, exact
    aggregate_kernel<<<agg_blocks, 256>>>(Wsc, bsc, score);
}